// round 14
// baseline (speedup 1.0000x reference)
#include <cuda_runtime.h>
#include <cstdint>

// Problem dims
#define NB 128   // batch (GEMM M)
#define NI 256   // in_features (GEMM K)
#define NH 128   // H (grid)
#define NO 32    // OUT (GEMM N)

#define AROW 272
#define BROW 272
#define NFIN 8   // number of tail-finisher CTAs

// Scratch: w[b][h][o]  (fully overwritten every launch -> no init needed)
__device__ float g_w[NB * NH * NO];
__device__ unsigned int g_done = 0;   // arrival counter (reset each launch)
__device__ unsigned int g_fin  = 0;   // finisher-done counter

// RNA round-to-tf32 bit trick (R12-validated): HMMA truncates low 13 mantissa
// bits; values are >= 0 so +0x1000 == cvt.rna.tf32.
static __device__ __forceinline__ uint32_t tf32_rna_bits(float f) {
    return __float_as_uint(f) + 0x1000u;
}

static __device__ __forceinline__ void mma_tf32(
    float d[4], uint32_t a0, uint32_t a1, uint32_t a2, uint32_t a3,
    uint32_t b0, uint32_t b1)
{
    asm volatile(
        "mma.sync.aligned.m16n8k8.row.col.f32.tf32.tf32.f32 "
        "{%0,%1,%2,%3}, {%4,%5,%6,%7}, {%8,%9}, {%0,%1,%2,%3};"
        : "+f"(d[0]), "+f"(d[1]), "+f"(d[2]), "+f"(d[3])
        : "r"(a0), "r"(a1), "r"(a2), "r"(a3), "r"(b0), "r"(b1));
}

// ---------------------------------------------------------------------------
// Single kernel, ONE CTA per h (128 CTAs = single wave).
//   Part 1: R13-proven permuted-K HMMA TF32 GEMM -> g_w[b][h][o].
//   Tail:   last-8-arriving CTAs each finish 16 b-rows (no one else waits).
// ---------------------------------------------------------------------------
__global__ __launch_bounds__(512, 1) void order1_all(
    const float* __restrict__ input,      // [NB][NI]
    const float* __restrict__ sigma_psi,  // [NI][NH][NO]
    const float* __restrict__ chi,        // [NI][NH]
    const float* __restrict__ sigma_eps,  // [NH][NO]
    const float* __restrict__ eta,        // [NH][NO]
    const float* __restrict__ mu_phi,     // [NO]
    const float* __restrict__ sigma_phi,  // [NO]
    float* __restrict__ out, int out_size)
{
    extern __shared__ uint32_t usmem[];
    uint32_t* As   = usmem;                      // [NB][AROW] tf32 bits
    uint32_t* Bs   = usmem + NB * AROW;          // [NO][BROW] tf32 bits
    float*    sChi = reinterpret_cast<float*>(Bs + NO * BROW);  // [NI]

    const int h    = blockIdx.x;
    const int tid  = threadIdx.x;
    const int wid  = tid >> 5;
    const int lane = tid & 31;

    // ---- Stage chi slice (256 scattered LDG once, instead of 2048) ----
    if (tid < NI) sChi[tid] = chi[tid * NH + h];

    // ---- Phase 1: Bs[o][perm(i)] = tf32(sigma_psi[i,h,o]^2) ----
    {
        const float4* sp4 = reinterpret_cast<const float4*>(sigma_psi);
#pragma unroll
        for (int k = 0; k < 4; k++) {
            int idx4 = tid + k * 512;          // 0..2047
            int i  = idx4 >> 3;
            int o4 = idx4 & 7;
            float4 v = sp4[(i * NH + h) * 8 + o4];
            const int pc = (i & 3) * 68 + (i >> 2);   // permuted column
            Bs[(o4 * 4 + 0) * BROW + pc] = tf32_rna_bits(v.x * v.x);
            Bs[(o4 * 4 + 1) * BROW + pc] = tf32_rna_bits(v.y * v.y);
            Bs[(o4 * 4 + 2) * BROW + pc] = tf32_rna_bits(v.z * v.z);
            Bs[(o4 * 4 + 3) * BROW + pc] = tf32_rna_bits(v.w * v.w);
        }
    }
    __syncthreads();   // sChi ready (and Bs stores ordered before MMA sync later)

    // ---- Phase 2: As[b][perm(i)] = tf32((chi[i,h]-x[b,i])^2) ----
    {
        const int iq = tid & 63;   // i-quad: i = 4*iq + j
        const int bb = tid >> 6;   // 0..7 (uniform within warp)
        const int i  = iq * 4;
        const float4 c4 = reinterpret_cast<const float4*>(sChi)[iq];  // LDS.128
#pragma unroll 4
        for (int k = 0; k < 16; k++) {
            const int b = bb + 8 * k;
            float4 x4 = *reinterpret_cast<const float4*>(input + b * NI + i);
            float d0 = c4.x - x4.x, d1 = c4.y - x4.y;
            float d2 = c4.z - x4.z, d3 = c4.w - x4.w;
            uint32_t* row = As + b * AROW + iq;   // perm(4iq+j) = j*68 + iq
            row[0 * 68] = tf32_rna_bits(d0 * d0);
            row[1 * 68] = tf32_rna_bits(d1 * d1);
            row[2 * 68] = tf32_rna_bits(d2 * d2);
            row[3 * 68] = tf32_rna_bits(d3 * d3);
        }
    }
    __syncthreads();

    // ---- MMA: 16 pair-steps; per pair-step 4x LDS.128 + 4x HMMA ----
    {
        const int m  = wid >> 1;
        const int nh = wid & 1;
        const int g  = lane >> 2;
        const int c  = lane & 3;

        const uint32_t* pa0 = As + (m * 16 + g) * AROW + c * 68;
        const uint32_t* pa1 = pa0 + 8 * AROW;
        const uint32_t* pb0 = Bs + (nh * 16 + g) * BROW + c * 68;
        const uint32_t* pb1 = pb0 + 8 * BROW;

        float acc0[4] = {0.f, 0.f, 0.f, 0.f};
        float acc1[4] = {0.f, 0.f, 0.f, 0.f};

#pragma unroll
        for (int t2 = 0; t2 < 16; t2++) {
            const int off = 4 * t2;
            uint4 la0 = *reinterpret_cast<const uint4*>(pa0 + off);
            uint4 la1 = *reinterpret_cast<const uint4*>(pa1 + off);
            uint4 lb0 = *reinterpret_cast<const uint4*>(pb0 + off);
            uint4 lb1 = *reinterpret_cast<const uint4*>(pb1 + off);
            mma_tf32(acc0, la0.x, la1.x, la0.y, la1.y, lb0.x, lb0.y);
            mma_tf32(acc1, la0.x, la1.x, la0.y, la1.y, lb1.x, lb1.y);
            mma_tf32(acc0, la0.z, la1.z, la0.w, la1.w, lb0.z, lb0.w);
            mma_tf32(acc1, la0.z, la1.z, la0.w, la1.w, lb1.z, lb1.w);
        }

        // ---- Epilogue (R10-proven fragment map): w = 1/(s+eps^2) ----
        const int r0 = m * 16 + g;
        const int r1 = r0 + 8;
        const int o0 = nh * 16 + c * 2;
        const int o1 = o0 + 8;

        const float* se = sigma_eps + h * NO;
        float e00 = se[o0], e01 = se[o0 + 1], e10 = se[o1], e11 = se[o1 + 1];
        e00 *= e00; e01 *= e01; e10 *= e10; e11 *= e11;

        float* g0 = g_w + (r0 * NH + h) * NO;
        float* g1 = g_w + (r1 * NH + h) * NO;

        *reinterpret_cast<float2*>(g0 + o0) =
            make_float2(__fdividef(1.f, acc0[0] + e00),
                        __fdividef(1.f, acc0[1] + e01));
        *reinterpret_cast<float2*>(g1 + o0) =
            make_float2(__fdividef(1.f, acc0[2] + e00),
                        __fdividef(1.f, acc0[3] + e01));
        *reinterpret_cast<float2*>(g0 + o1) =
            make_float2(__fdividef(1.f, acc1[0] + e10),
                        __fdividef(1.f, acc1[1] + e11));
        *reinterpret_cast<float2*>(g1 + o1) =
            make_float2(__fdividef(1.f, acc1[2] + e10),
                        __fdividef(1.f, acc1[3] + e11));
    }

    // =========== Arrival: last NFIN CTAs become finishers ===========
    __threadfence();       // release g_w stores
    __syncthreads();
    __shared__ unsigned int s_rank;
    if (tid == 0) s_rank = atomicAdd(&g_done, 1u);
    __syncthreads();
    if (s_rank < (unsigned)(NH - NFIN)) return;   // no wait for most CTAs
    const int fid = (int)s_rank - (NH - NFIN);    // 0..NFIN-1

    // Wait for ALL arrivals (only NFIN CTAs spin; 1 wave -> deadlock-free)
    if (tid == 0) {
        unsigned int v;
        asm volatile("ld.acquire.gpu.global.u32 %0, [%1];"
                     : "=r"(v) : "l"(&g_done));
        while (v < (unsigned)NH) {
            __nanosleep(64);
            asm volatile("ld.acquire.gpu.global.u32 %0, [%1];"
                         : "=r"(v) : "l"(&g_done));
        }
    }
    __syncthreads();

    // ---- Stage eta [NH][NO] into smem (16 KB; As region is dead now) ----
    float4* sEta = reinterpret_cast<float4*>(usmem);
    {
        const float4* eta4 = reinterpret_cast<const float4*>(eta);
        sEta[tid]       = eta4[tid];
        sEta[tid + 512] = eta4[tid + 512];
    }
    __syncthreads();

    // ---- Each warp finishes one b: reduce 128 h x 32 o ----
    {
        const int b = fid * 16 + wid;
        const float4* row4 = reinterpret_cast<const float4*>(g_w + b * NH * NO);

        float4 sw  = make_float4(0.f, 0.f, 0.f, 0.f);
        float4 swe = make_float4(0.f, 0.f, 0.f, 0.f);
#pragma unroll
        for (int k = 0; k < 32; k++) {
            float4 w4 = __ldcg(row4 + 32 * k + lane);   // coalesced L2 read
            float4 e4 = sEta[32 * k + lane];
            sw.x += w4.x; sw.y += w4.y; sw.z += w4.z; sw.w += w4.w;
            swe.x += w4.x * e4.x; swe.y += w4.y * e4.y;
            swe.z += w4.z * e4.z; swe.w += w4.w * e4.w;
        }
        // reduce over lane bits 3,4 (h-groups); o4 = lane&7 preserved
#pragma unroll
        for (int mm = 8; mm <= 16; mm <<= 1) {
            sw.x += __shfl_xor_sync(0xffffffffu, sw.x, mm);
            sw.y += __shfl_xor_sync(0xffffffffu, sw.y, mm);
            sw.z += __shfl_xor_sync(0xffffffffu, sw.z, mm);
            sw.w += __shfl_xor_sync(0xffffffffu, sw.w, mm);
            swe.x += __shfl_xor_sync(0xffffffffu, swe.x, mm);
            swe.y += __shfl_xor_sync(0xffffffffu, swe.y, mm);
            swe.z += __shfl_xor_sync(0xffffffffu, swe.z, mm);
            swe.w += __shfl_xor_sync(0xffffffffu, swe.w, mm);
        }
        if (lane < 8) {
            const int o = lane * 4;
            float4 mp = *reinterpret_cast<const float4*>(mu_phi + o);
            float4 sp = *reinterpret_cast<const float4*>(sigma_phi + o);
            float swa[4]  = {sw.x, sw.y, sw.z, sw.w};
            float swea[4] = {swe.x, swe.y, swe.z, swe.w};
            float mpa[4]  = {mp.x, mp.y, mp.z, mp.w};
            float spa[4]  = {sp.x, sp.y, sp.z, sp.w};
            float pm[4], ps[4];
#pragma unroll
            for (int cc = 0; cc < 4; cc++) {
                float sp2 = spa[cc] * spa[cc];
                float inv = __fdividef(1.0f, fmaf(sp2, swa[cc], 1.0f));
                pm[cc] = (mpa[cc] + sp2 * swea[cc]) * inv;
                ps[cc] = sp2 * inv;
            }
            *reinterpret_cast<float4*>(out + b * NO + o) =
                make_float4(pm[0], pm[1], pm[2], pm[3]);
            if (out_size >= 2 * NB * NO)
                *reinterpret_cast<float4*>(out + NB * NO + b * NO + o) =
                    make_float4(ps[0], ps[1], ps[2], ps[3]);
        }
    }

    // ---- Finisher-done counter: last finisher resets for next replay ----
    __syncthreads();
    if (tid == 0) {
        if (atomicAdd(&g_fin, 1u) == (unsigned)NFIN - 1u) {
            g_done = 0u;
            g_fin  = 0u;
            __threadfence();
        }
    }
}

extern "C" void kernel_launch(void* const* d_in, const int* in_sizes, int n_in,
                              void* d_out, int out_size) {
    const float* input     = (const float*)d_in[0];
    const float* sigma_psi = (const float*)d_in[1];
    const float* chi       = (const float*)d_in[2];
    const float* sigma_eps = (const float*)d_in[3];
    const float* eta       = (const float*)d_in[4];
    const float* mu_phi    = (const float*)d_in[5];
    const float* sigma_phi = (const float*)d_in[6];

    // As + Bs + sChi
    const int smemA =
        (NB * AROW + NO * BROW) * (int)sizeof(uint32_t) + NI * (int)sizeof(float);
    cudaFuncSetAttribute(order1_all,
                         cudaFuncAttributeMaxDynamicSharedMemorySize, smemA);

    order1_all<<<NH, 512, smemA>>>(input, sigma_psi, chi, sigma_eps,
                                   eta, mu_phi, sigma_phi,
                                   (float*)d_out, out_size);
}

// round 16
// speedup vs baseline: 1.1759x; 1.1759x over previous
#include <cuda_runtime.h>
#include <cstdint>

// Problem dims
#define NB 128   // batch (GEMM M)
#define NI 256   // in_features (GEMM K)
#define NH 128   // H (grid)
#define NO 32    // OUT (GEMM N)

#define AROW 272  // row strides (words): even -> LDS.128 aligned (R13-proven)
#define BROW 272

// Scratch: w[b][h][o]  (fully overwritten every launch -> no init needed)
__device__ float g_w[NB * NH * NO];

// RNA round-to-tf32 bit trick (R12-validated)
static __device__ __forceinline__ uint32_t tf32_rna_bits(float f) {
    return __float_as_uint(f) + 0x1000u;
}

static __device__ __forceinline__ void mma_tf32(
    float d[4], uint32_t a0, uint32_t a1, uint32_t a2, uint32_t a3,
    uint32_t b0, uint32_t b1)
{
    asm volatile(
        "mma.sync.aligned.m16n8k8.row.col.f32.tf32.tf32.f32 "
        "{%0,%1,%2,%3}, {%4,%5,%6,%7}, {%8,%9}, {%0,%1,%2,%3};"
        : "+f"(d[0]), "+f"(d[1]), "+f"(d[2]), "+f"(d[3])
        : "r"(a0), "r"(a1), "r"(a2), "r"(a3), "r"(b0), "r"(b1));
}

// ---------------------------------------------------------------------------
// Kernel A: ONE CTA per h, 512 threads. R13-proven permuted-K HMMA TF32 GEMM
// (+ chi smem staging, + PDL trigger after smem build).
// ---------------------------------------------------------------------------
__global__ __launch_bounds__(512, 1) void order1_main(
    const float* __restrict__ input,      // [NB][NI]
    const float* __restrict__ sigma_psi,  // [NI][NH][NO]
    const float* __restrict__ chi,        // [NI][NH]
    const float* __restrict__ sigma_eps)  // [NH][NO]
{
    extern __shared__ uint32_t usmem[];
    uint32_t* As   = usmem;                      // [NB][AROW]
    uint32_t* Bs   = usmem + NB * AROW;          // [NO][BROW]
    float*    sChi = reinterpret_cast<float*>(Bs + NO * BROW);  // [NI]

    const int h    = blockIdx.x;
    const int tid  = threadIdx.x;
    const int wid  = tid >> 5;
    const int lane = tid & 31;

    // ---- Stage chi slice once (256 scattered LDG instead of 2048) ----
    if (tid < NI) sChi[tid] = chi[tid * NH + h];

    // ---- Phase 1 (R13-proven): Bs[o][perm(i)] = tf32(sigma_psi^2) ----
    {
        const float4* sp4 = reinterpret_cast<const float4*>(sigma_psi);
#pragma unroll
        for (int k = 0; k < 4; k++) {
            int idx4 = tid + k * 512;          // 0..2047
            int i  = idx4 >> 3;
            int o4 = idx4 & 7;
            float4 v = sp4[(i * NH + h) * 8 + o4];
            const int pc = (i & 3) * 68 + (i >> 2);   // permuted column
            Bs[(o4 * 4 + 0) * BROW + pc] = tf32_rna_bits(v.x * v.x);
            Bs[(o4 * 4 + 1) * BROW + pc] = tf32_rna_bits(v.y * v.y);
            Bs[(o4 * 4 + 2) * BROW + pc] = tf32_rna_bits(v.z * v.z);
            Bs[(o4 * 4 + 3) * BROW + pc] = tf32_rna_bits(v.w * v.w);
        }
    }
    __syncthreads();   // sChi + Bs ready

    // ---- Phase 2 (R13-proven): As[b][perm(i)] = tf32((chi-x)^2) ----
    {
        const int iq = tid & 63;
        const int bb = tid >> 6;
        const int i  = iq * 4;
        const float4 c4 = reinterpret_cast<const float4*>(sChi)[iq];  // LDS.128
#pragma unroll 4
        for (int k = 0; k < 16; k++) {
            const int b = bb + 8 * k;
            float4 x4 = *reinterpret_cast<const float4*>(input + b * NI + i);
            float d0 = c4.x - x4.x, d1 = c4.y - x4.y;
            float d2 = c4.z - x4.z, d3 = c4.w - x4.w;
            uint32_t* row = As + b * AROW + iq;   // perm(4iq+j) = j*68 + iq
            row[0 * 68] = tf32_rna_bits(d0 * d0);
            row[1 * 68] = tf32_rna_bits(d1 * d1);
            row[2 * 68] = tf32_rna_bits(d2 * d2);
            row[3 * 68] = tf32_rna_bits(d3 * d3);
        }
    }
    __syncthreads();

    // PDL: let the finish kernel launch + stage its smem while we MMA.
    asm volatile("griddepcontrol.launch_dependents;" ::: "memory");

    // ---- MMA: 16 pair-steps; 4x LDS.128 + 4x HMMA each (R13-proven) ----
    {
        const int m  = wid >> 1;
        const int nh = wid & 1;
        const int g  = lane >> 2;
        const int c  = lane & 3;

        const uint32_t* pa0 = As + (m * 16 + g) * AROW + c * 68;
        const uint32_t* pa1 = pa0 + 8 * AROW;
        const uint32_t* pb0 = Bs + (nh * 16 + g) * BROW + c * 68;
        const uint32_t* pb1 = pb0 + 8 * BROW;

        float acc0[4] = {0.f, 0.f, 0.f, 0.f};
        float acc1[4] = {0.f, 0.f, 0.f, 0.f};

#pragma unroll
        for (int t2 = 0; t2 < 16; t2++) {
            const int off = 4 * t2;
            uint4 la0 = *reinterpret_cast<const uint4*>(pa0 + off);
            uint4 la1 = *reinterpret_cast<const uint4*>(pa1 + off);
            uint4 lb0 = *reinterpret_cast<const uint4*>(pb0 + off);
            uint4 lb1 = *reinterpret_cast<const uint4*>(pb1 + off);
            mma_tf32(acc0, la0.x, la1.x, la0.y, la1.y, lb0.x, lb0.y);
            mma_tf32(acc1, la0.x, la1.x, la0.y, la1.y, lb1.x, lb1.y);
            mma_tf32(acc0, la0.z, la1.z, la0.w, la1.w, lb0.z, lb0.w);
            mma_tf32(acc1, la0.z, la1.z, la0.w, la1.w, lb1.z, lb1.w);
        }

        // ---- Epilogue (R10-proven fragment map): w = 1/(s+eps^2) ----
        const int r0 = m * 16 + g;
        const int r1 = r0 + 8;
        const int o0 = nh * 16 + c * 2;
        const int o1 = o0 + 8;

        const float* se = sigma_eps + h * NO;
        float e00 = se[o0], e01 = se[o0 + 1], e10 = se[o1], e11 = se[o1 + 1];
        e00 *= e00; e01 *= e01; e10 *= e10; e11 *= e11;

        float* g0 = g_w + (r0 * NH + h) * NO;
        float* g1 = g_w + (r1 * NH + h) * NO;

        *reinterpret_cast<float2*>(g0 + o0) =
            make_float2(__fdividef(1.f, acc0[0] + e00),
                        __fdividef(1.f, acc0[1] + e01));
        *reinterpret_cast<float2*>(g1 + o0) =
            make_float2(__fdividef(1.f, acc0[2] + e00),
                        __fdividef(1.f, acc0[3] + e01));
        *reinterpret_cast<float2*>(g0 + o1) =
            make_float2(__fdividef(1.f, acc1[0] + e10),
                        __fdividef(1.f, acc1[1] + e11));
        *reinterpret_cast<float2*>(g1 + o1) =
            make_float2(__fdividef(1.f, acc1[2] + e10),
                        __fdividef(1.f, acc1[3] + e11));
    }
}

// ---------------------------------------------------------------------------
// Kernel B: CTA per b (R8-proven body). PDL: stage eta + priors BEFORE the
// grid-dep wait so the preamble overlaps main's MMA phase.
// ---------------------------------------------------------------------------
__global__ __launch_bounds__(512) void order1_finish(
    const float* __restrict__ eta,        // [NH][NO]
    const float* __restrict__ mu_phi,     // [NO]
    const float* __restrict__ sigma_phi,  // [NO]
    float* __restrict__ out, int out_size)
{
    __shared__ float4 sEta[1024];   // 16 KB
    __shared__ float4 sA[16 * 8];
    __shared__ float4 sB[16 * 8];

    const int b = blockIdx.x;
    const int t = threadIdx.x;
    const int wid = t >> 5;
    const int l = t & 31;

    // ---- Preamble (overlaps main): stage eta, preload prior params ----
    {
        const float4* eta4 = reinterpret_cast<const float4*>(eta);
        sEta[t]       = eta4[t];
        sEta[t + 512] = eta4[t + 512];
    }
    float4 mp = make_float4(0.f, 0.f, 0.f, 0.f);
    float4 sp = make_float4(0.f, 0.f, 0.f, 0.f);
    if (t < 8) {
        mp = *reinterpret_cast<const float4*>(mu_phi + t * 4);
        sp = *reinterpret_cast<const float4*>(sigma_phi + t * 4);
    }
    __syncthreads();

    // ---- Wait for main's completion (no-op if launched without PDL) ----
    asm volatile("griddepcontrol.wait;" ::: "memory");

    const float4* row4 = reinterpret_cast<const float4*>(g_w + b * NH * NO);

    float4 sw  = make_float4(0.f, 0.f, 0.f, 0.f);
    float4 swe = make_float4(0.f, 0.f, 0.f, 0.f);
#pragma unroll
    for (int rep = 0; rep < 2; rep++) {
        int idx = t + rep * 512;
        float4 w4 = __ldcg(row4 + idx);
        float4 e4 = sEta[idx];
        sw.x += w4.x; sw.y += w4.y; sw.z += w4.z; sw.w += w4.w;
        swe.x += w4.x * e4.x; swe.y += w4.y * e4.y;
        swe.z += w4.z * e4.z; swe.w += w4.w * e4.w;
    }

#pragma unroll
    for (int m = 8; m <= 16; m <<= 1) {
        sw.x += __shfl_xor_sync(0xffffffffu, sw.x, m);
        sw.y += __shfl_xor_sync(0xffffffffu, sw.y, m);
        sw.z += __shfl_xor_sync(0xffffffffu, sw.z, m);
        sw.w += __shfl_xor_sync(0xffffffffu, sw.w, m);
        swe.x += __shfl_xor_sync(0xffffffffu, swe.x, m);
        swe.y += __shfl_xor_sync(0xffffffffu, swe.y, m);
        swe.z += __shfl_xor_sync(0xffffffffu, swe.z, m);
        swe.w += __shfl_xor_sync(0xffffffffu, swe.w, m);
    }
    if (l < 8) {
        sA[wid * 8 + l] = sw;
        sB[wid * 8 + l] = swe;
    }
    __syncthreads();

    if (t < 8) {
        float4 a = sA[t], bb = sB[t];
#pragma unroll
        for (int k = 1; k < 16; k++) {
            float4 a2 = sA[k * 8 + t], b2 = sB[k * 8 + t];
            a.x += a2.x; a.y += a2.y; a.z += a2.z; a.w += a2.w;
            bb.x += b2.x; bb.y += b2.y; bb.z += b2.z; bb.w += b2.w;
        }
        const int o = t * 4;
        float swa[4]  = {a.x, a.y, a.z, a.w};
        float swea[4] = {bb.x, bb.y, bb.z, bb.w};
        float mpa[4]  = {mp.x, mp.y, mp.z, mp.w};
        float spa[4]  = {sp.x, sp.y, sp.z, sp.w};
        float pm[4], ps[4];
#pragma unroll
        for (int cc = 0; cc < 4; cc++) {
            float sp2 = spa[cc] * spa[cc];
            float inv = __fdividef(1.0f, fmaf(sp2, swa[cc], 1.0f));
            pm[cc] = (mpa[cc] + sp2 * swea[cc]) * inv;
            ps[cc] = sp2 * inv;
        }
        *reinterpret_cast<float4*>(out + b * NO + o) =
            make_float4(pm[0], pm[1], pm[2], pm[3]);
        if (out_size >= 2 * NB * NO)
            *reinterpret_cast<float4*>(out + NB * NO + b * NO + o) =
                make_float4(ps[0], ps[1], ps[2], ps[3]);
    }
}

extern "C" void kernel_launch(void* const* d_in, const int* in_sizes, int n_in,
                              void* d_out, int out_size) {
    const float* input     = (const float*)d_in[0];
    const float* sigma_psi = (const float*)d_in[1];
    const float* chi       = (const float*)d_in[2];
    const float* sigma_eps = (const float*)d_in[3];
    const float* eta       = (const float*)d_in[4];
    const float* mu_phi    = (const float*)d_in[5];
    const float* sigma_phi = (const float*)d_in[6];
    float* out = (float*)d_out;

    const int smemA =
        (NB * AROW + NO * BROW) * (int)sizeof(uint32_t) + NI * (int)sizeof(float);
    cudaFuncSetAttribute(order1_main,
                         cudaFuncAttributeMaxDynamicSharedMemorySize, smemA);

    order1_main<<<NH, 512, smemA>>>(input, sigma_psi, chi, sigma_eps);

    // Finish with PDL so its launch+preamble overlap main's MMA phase.
    cudaLaunchConfig_t cfg = {};
    cfg.gridDim  = dim3(NB);
    cfg.blockDim = dim3(512);
    cfg.dynamicSmemBytes = 0;
    cudaLaunchAttribute attrs[1];
    attrs[0].id = cudaLaunchAttributeProgrammaticStreamSerialization;
    attrs[0].val.programmaticStreamSerializationAllowed = 1;
    cfg.attrs = attrs;
    cfg.numAttrs = 1;
    cudaError_t e = cudaLaunchKernelEx(&cfg, order1_finish,
                                       eta, mu_phi, sigma_phi, out, out_size);
    if (e != cudaSuccess) {
        // Fallback: plain serialized launch (griddepcontrol.wait is a no-op).
        order1_finish<<<NB, 512>>>(eta, mu_phi, sigma_phi, out, out_size);
    }
}